// round 2
// baseline (speedup 1.0000x reference)
#include <cuda_runtime.h>
#include <cuda_bf16.h>
#include <stdint.h>

// Problem constants (fixed by the reference)
#define BATCH 1024
#define IN_SIZE 2048
#define OUT_SIZE 2048
#define EMAX 131072
#define NGROUPS 64            // output groups of 32
#define NKEYS (NGROUPS * IN_SIZE)   // 131072 sort buckets: (o>>5)*2048 + in

// -------- device scratch (no allocations allowed) --------
__device__ float g_xT[IN_SIZE * BATCH];      // 8 MB : x transposed [in][batch]
__device__ float g_outT[OUT_SIZE * BATCH];   // 8 MB : out transposed [out][batch]
__device__ int      g_cnt[NKEYS];
__device__ int      g_off[NKEYS];            // exclusive offsets (final after K3)
__device__ int      g_cur[NKEYS];
__device__ int      g_bsum[128];             // per-block sums for scan
__device__ int      g_bsumx[128];            // exclusive-scanned block sums
__device__ unsigned g_srt_rec[EMAX];         // in(11b) | slot(5b)<<11
__device__ float    g_srt_w[EMAX];
__device__ int      g_idx64;

__device__ __forceinline__ int fetch_idx(const void* p, int e, int is64) {
    if (is64) return (int)(((const long long*)p)[e]);
    return ((const int*)p)[e];
}

// -------- 1. detect index dtype + zero counters (fused) --------
__global__ void setup_kernel(const void* in_idx, int E) {
    int t = blockIdx.x * blockDim.x + threadIdx.x;
    if (t < NKEYS) g_cnt[t] = 0;
    if (t == 0) {
        const long long* q = (const long long*)in_idx;
        int n = E < 32 ? E : 32;
        bool ok64 = true;
        for (int k = 0; k < n; k++) {
            long long v = q[k];
            if (v < 0 || v >= IN_SIZE) { ok64 = false; break; }
        }
        g_idx64 = ok64 ? 1 : 0;
    }
}

// -------- 2. histogram over composite key --------
__global__ void hist_kernel(const void* in_idx, const void* out_idx, int E) {
    int is64 = g_idx64;
    for (int e = blockIdx.x * blockDim.x + threadIdx.x; e < E;
         e += gridDim.x * blockDim.x) {
        int o = fetch_idx(out_idx, e, is64);
        int i = fetch_idx(in_idx, e, is64);
        int key = ((o >> 5) << 11) | i;
        atomicAdd(&g_cnt[key], 1);
    }
}

// -------- 3a. scan K1: per-block (1024 keys) exclusive scan + block sum -----
__global__ void scan_k1() {
    int gid = blockIdx.x * 1024 + threadIdx.x;
    int lane = threadIdx.x & 31;
    int wid = threadIdx.x >> 5;
    int v = g_cnt[gid];
    int x = v;
#pragma unroll
    for (int d = 1; d < 32; d <<= 1) {
        int y = __shfl_up_sync(0xFFFFFFFFu, x, d);
        if (lane >= d) x += y;
    }
    __shared__ int ws[32];
    if (lane == 31) ws[wid] = x;
    __syncthreads();
    if (wid == 0) {
        int s = ws[lane];
#pragma unroll
        for (int d = 1; d < 32; d <<= 1) {
            int y = __shfl_up_sync(0xFFFFFFFFu, s, d);
            if (lane >= d) s += y;
        }
        ws[lane] = s;
    }
    __syncthreads();
    int inc = x + (wid > 0 ? ws[wid - 1] : 0);
    g_off[gid] = inc - v;  // exclusive within block
    if (threadIdx.x == 1023) g_bsum[blockIdx.x] = inc;
}

// -------- 3b. scan K2: exclusive scan of 128 block sums ---------------------
__global__ void scan_k2() {
    int t = threadIdx.x;
    int lane = t & 31;
    int wid = t >> 5;
    int v = g_bsum[t];
    int x = v;
#pragma unroll
    for (int d = 1; d < 32; d <<= 1) {
        int y = __shfl_up_sync(0xFFFFFFFFu, x, d);
        if (lane >= d) x += y;
    }
    __shared__ int ws[4];
    if (lane == 31) ws[wid] = x;
    __syncthreads();
    int carry = 0;
#pragma unroll
    for (int k = 0; k < 4; k++) carry += (k < wid) ? ws[k] : 0;
    g_bsumx[t] = x + carry - v;  // exclusive
}

// -------- 3c. scan K3: add block offsets, init cursors ----------------------
__global__ void scan_k3() {
    int gid = blockIdx.x * 1024 + threadIdx.x;
    int o = g_off[gid] + g_bsumx[blockIdx.x];
    g_off[gid] = o;
    g_cur[gid] = o;
}

// -------- 4. scatter edges into key-sorted order ----------------------------
__global__ void scatter_kernel(const void* in_idx, const void* out_idx,
                               const float* w, int E) {
    int is64 = g_idx64;
    for (int e = blockIdx.x * blockDim.x + threadIdx.x; e < E;
         e += gridDim.x * blockDim.x) {
        int o = fetch_idx(out_idx, e, is64);
        int i = fetch_idx(in_idx, e, is64);
        int key = ((o >> 5) << 11) | i;
        int pos = atomicAdd(&g_cur[key], 1);
        g_srt_rec[pos] = (unsigned)(i | ((o & 31) << 11));
        g_srt_w[pos] = w[e];
    }
}

// -------- 5. transpose x [B][IN] -> xT [IN][B] --------
__global__ void transpose_x_kernel(const float* __restrict__ x) {
    __shared__ float tile[32][33];
    int ix = blockIdx.x * 32 + threadIdx.x;
    int ib = blockIdx.y * 32 + threadIdx.y;
#pragma unroll
    for (int j = 0; j < 4; j++)
        tile[threadIdx.y + 8 * j][threadIdx.x] = x[(ib + 8 * j) * IN_SIZE + ix];
    __syncthreads();
    int ob = blockIdx.y * 32 + threadIdx.x;
    int oi = blockIdx.x * 32 + threadIdx.y;
#pragma unroll
    for (int j = 0; j < 4; j++)
        g_xT[(oi + 8 * j) * BATCH + ob] = tile[threadIdx.x][threadIdx.y + 8 * j];
}

// -------- 6. main SpMM: block = (group of 32 outputs) x (batch half) --------
// Edges sorted by (group, in_idx): duplicate inputs are adjacent -> L1 hits.
// Accumulator slot selected by block-uniform 32-case switch (no divergence).

#define ACC_CASE(S) case S: a##S.x += wq * vq.x; a##S.y += wq * vq.y; break;
#define ACC_SWITCH(slot, wq, vq)                                   \
    switch (slot) {                                                \
        ACC_CASE(0)  ACC_CASE(1)  ACC_CASE(2)  ACC_CASE(3)         \
        ACC_CASE(4)  ACC_CASE(5)  ACC_CASE(6)  ACC_CASE(7)         \
        ACC_CASE(8)  ACC_CASE(9)  ACC_CASE(10) ACC_CASE(11)        \
        ACC_CASE(12) ACC_CASE(13) ACC_CASE(14) ACC_CASE(15)        \
        ACC_CASE(16) ACC_CASE(17) ACC_CASE(18) ACC_CASE(19)        \
        ACC_CASE(20) ACC_CASE(21) ACC_CASE(22) ACC_CASE(23)        \
        ACC_CASE(24) ACC_CASE(25) ACC_CASE(26) ACC_CASE(27)        \
        ACC_CASE(28) ACC_CASE(29) ACC_CASE(30) ACC_CASE(31)        \
    }

__global__ void __launch_bounds__(256) spmm_kernel(int E) {
    int g = blockIdx.x >> 1;        // output group (64)
    int chunk = blockIdx.x & 1;     // batch half
    int t = threadIdx.x;
    int s = g_off[g << 11];
    int e = (g == NGROUPS - 1) ? E : g_off[(g + 1) << 11];
    int bb = (chunk << 9) + (t << 1);  // batch base for this thread (float2)

    float2 a0 = {0,0}, a1 = {0,0}, a2 = {0,0}, a3 = {0,0};
    float2 a4 = {0,0}, a5 = {0,0}, a6 = {0,0}, a7 = {0,0};
    float2 a8 = {0,0}, a9 = {0,0}, a10 = {0,0}, a11 = {0,0};
    float2 a12 = {0,0}, a13 = {0,0}, a14 = {0,0}, a15 = {0,0};
    float2 a16 = {0,0}, a17 = {0,0}, a18 = {0,0}, a19 = {0,0};
    float2 a20 = {0,0}, a21 = {0,0}, a22 = {0,0}, a23 = {0,0};
    float2 a24 = {0,0}, a25 = {0,0}, a26 = {0,0}, a27 = {0,0};
    float2 a28 = {0,0}, a29 = {0,0}, a30 = {0,0}, a31 = {0,0};

    __shared__ unsigned sr[256];
    __shared__ float swt[256];

    for (int base = s; base < e; base += 256) {
        int m = e - base;
        if (m > 256) m = 256;
        if (t < m) { sr[t] = g_srt_rec[base + t]; swt[t] = g_srt_w[base + t]; }
        __syncthreads();
        int j = 0;
        // pipelined by 8: batch the gathers, then do the uniform switches
        for (; j + 8 <= m; j += 8) {
            unsigned r[8]; float w[8]; float2 v[8];
#pragma unroll
            for (int q = 0; q < 8; q++) {
                r[q] = sr[j + q];
                w[q] = swt[j + q];
                v[q] = *reinterpret_cast<const float2*>(
                    &g_xT[((r[q] & 2047) << 10) + bb]);
            }
#pragma unroll
            for (int q = 0; q < 8; q++) {
                int slot = r[q] >> 11;
                float wq = w[q];
                float2 vq = v[q];
                ACC_SWITCH(slot, wq, vq)
            }
        }
        for (; j < m; j++) {
            unsigned rq = sr[j];
            float wq = swt[j];
            float2 vq = *reinterpret_cast<const float2*>(
                &g_xT[((rq & 2047) << 10) + bb]);
            int slot = rq >> 11;
            ACC_SWITCH(slot, wq, vq)
        }
        __syncthreads();
    }

    int obase = g << 5;
#define STORE_SLOT(S)                                                          \
    *reinterpret_cast<float2*>(&g_outT[(obase + S) * BATCH + bb]) = a##S;
    STORE_SLOT(0)  STORE_SLOT(1)  STORE_SLOT(2)  STORE_SLOT(3)
    STORE_SLOT(4)  STORE_SLOT(5)  STORE_SLOT(6)  STORE_SLOT(7)
    STORE_SLOT(8)  STORE_SLOT(9)  STORE_SLOT(10) STORE_SLOT(11)
    STORE_SLOT(12) STORE_SLOT(13) STORE_SLOT(14) STORE_SLOT(15)
    STORE_SLOT(16) STORE_SLOT(17) STORE_SLOT(18) STORE_SLOT(19)
    STORE_SLOT(20) STORE_SLOT(21) STORE_SLOT(22) STORE_SLOT(23)
    STORE_SLOT(24) STORE_SLOT(25) STORE_SLOT(26) STORE_SLOT(27)
    STORE_SLOT(28) STORE_SLOT(29) STORE_SLOT(30) STORE_SLOT(31)
#undef STORE_SLOT
}

// -------- 7. transpose outT [OUT][B] -> out [B][OUT] --------
__global__ void transpose_out_kernel(float* __restrict__ out) {
    __shared__ float tile[32][33];
    int ib = blockIdx.x * 32 + threadIdx.x;
    int io = blockIdx.y * 32 + threadIdx.y;
#pragma unroll
    for (int j = 0; j < 4; j++)
        tile[threadIdx.y + 8 * j][threadIdx.x] =
            g_outT[(io + 8 * j) * BATCH + ib];
    __syncthreads();
    int oo = blockIdx.y * 32 + threadIdx.x;
    int ob = blockIdx.x * 32 + threadIdx.y;
#pragma unroll
    for (int j = 0; j < 4; j++)
        out[(ob + 8 * j) * OUT_SIZE + oo] = tile[threadIdx.x][threadIdx.y + 8 * j];
}

extern "C" void kernel_launch(void* const* d_in, const int* in_sizes, int n_in,
                              void* d_out, int out_size) {
    const float* x       = (const float*)d_in[0];
    const float* weights = (const float*)d_in[1];
    const void*  in_idx  = d_in[2];
    const void*  out_idx = d_in[3];
    float* out = (float*)d_out;
    int E = in_sizes[1];
    if (E > EMAX) E = EMAX;

    // 1. detect dtype + zero 131072 counters
    setup_kernel<<<NKEYS / 256, 256>>>(in_idx, E);

    // 2. histogram over (group, in) key
    hist_kernel<<<256, 256>>>(in_idx, out_idx, E);

    // 3. hierarchical exclusive scan over 131072 counters
    scan_k1<<<128, 1024>>>();
    scan_k2<<<1, 128>>>();
    scan_k3<<<128, 1024>>>();

    // 4. scatter edges sorted by (group, in)
    scatter_kernel<<<256, 256>>>(in_idx, out_idx, weights, E);

    // 5. transpose x -> xT
    {
        dim3 grid(IN_SIZE / 32, BATCH / 32);
        dim3 block(32, 8);
        transpose_x_kernel<<<grid, block>>>(x);
    }

    // 6. main gather-reduce: 64 groups x 2 batch halves = 128 blocks
    spmm_kernel<<<NGROUPS * 2, 256>>>(E);

    // 7. transpose outT -> out
    {
        dim3 grid(BATCH / 32, OUT_SIZE / 32);
        dim3 block(32, 8);
        transpose_out_kernel<<<grid, block>>>(out);
    }
}